// round 1
// baseline (speedup 1.0000x reference)
#include <cuda_runtime.h>

// Rayleigh-Bénard RHS: 6 fields [6, NX, NY, NZ] f32, z contiguous.
// Periodic x/y (2nd-order central), non-periodic z (central interior,
// 2nd-order one-sided at walls). Output tendencies [6, NX, NY, NZ].

#define NXg 256
#define NYg 256
#define NZg 128

__device__ __forceinline__ float d1z_sm(const float* __restrict__ s, int k, float inv2dz) {
    if (k == 0)        return (-3.0f * s[0] + 4.0f * s[1] - s[2]) * inv2dz;
    if (k == NZg - 1)  return ( 3.0f * s[NZg-1] - 4.0f * s[NZg-2] + s[NZg-3]) * inv2dz;
    return (s[k+1] - s[k-1]) * inv2dz;
}

__device__ __forceinline__ float d2z_sm(const float* __restrict__ s, int k, float invdz2) {
    if (k == 0)        return (2.0f*s[0] - 5.0f*s[1] + 4.0f*s[2] - s[3]) * invdz2;
    if (k == NZg - 1)  return (2.0f*s[NZg-1] - 5.0f*s[NZg-2] + 4.0f*s[NZg-3] - s[NZg-4]) * invdz2;
    return (s[k+1] - 2.0f*s[k] + s[k-1]) * invdz2;
}

__global__ __launch_bounds__(NZg)
void rbm_rhs_kernel(const float* __restrict__ st, float* __restrict__ out) {
    const int k = threadIdx.x;        // z, contiguous
    const int j = blockIdx.x;         // y
    const int i = blockIdx.y;         // x

    constexpr int PLANE = NYg * NZg;        // x stride
    constexpr int FS    = NXg * NYg * NZg;  // field stride

    // physics / grid constants
    constexpr float CP = 1004.0f, CVc = 717.0f, MU = 1.8e-5f, KTH = 0.025f, Gc = 9.8f;
    constexpr float Rg = CP - CVc;                 // 287
    constexpr float DX = 1.0f / NXg, DY = 1.0f / NYg, DZ = 1.0f / (NZg - 1);
    const float INV2DX = 0.5f / DX, INV2DY = 0.5f / DY, INV2DZ = 0.5f / DZ;
    const float INVDX2 = 1.0f / (DX * DX), INVDY2 = 1.0f / (DY * DY), INVDZ2 = 1.0f / (DZ * DZ);

    const int ipx = ((i + 1) & (NXg - 1)) * PLANE + j * NZg + k;
    const int imx = ((i - 1) & (NXg - 1)) * PLANE + j * NZg + k;
    const int jpy = i * PLANE + ((j + 1) & (NYg - 1)) * NZg + k;
    const int jmy = i * PLANE + ((j - 1) & (NYg - 1)) * NZg + k;
    const int idx = i * PLANE + j * NZg + k;

    __shared__ float s[6][NZg];

    float ctr[6], fxp[6], fxm[6], fyp[6], fym[6];
#pragma unroll
    for (int f = 0; f < 6; f++) {
        const float* p = st + f * FS;
        ctr[f] = __ldg(p + idx);
        s[f][k] = ctr[f];
        fxp[f] = __ldg(p + ipx);
        fxm[f] = __ldg(p + imx);
        fyp[f] = __ldg(p + jpy);
        fym[f] = __ldg(p + jmy);
    }
    __syncthreads();

    const float u = ctr[0], v = ctr[1], w = ctr[2], rou = ctr[3], T = ctr[4], c = ctr[5];
    const float inv_rou = 1.0f / rou;

    // ---- pressure derivatives: p = R * rou * T ----
    const float dpdx = (Rg * fxp[3] * fxp[4] - Rg * fxm[3] * fxm[4]) * INV2DX;
    const float dpdy = (Rg * fyp[3] * fyp[4] - Rg * fym[3] * fym[4]) * INV2DY;
    float dpdz;
    {
        const float* sr = s[3];
        const float* sT = s[4];
        if (k == 0) {
            dpdz = (-3.0f * Rg * sr[0] * sT[0] + 4.0f * Rg * sr[1] * sT[1]
                    - Rg * sr[2] * sT[2]) * INV2DZ;
        } else if (k == NZg - 1) {
            dpdz = (3.0f * Rg * sr[NZg-1] * sT[NZg-1] - 4.0f * Rg * sr[NZg-2] * sT[NZg-2]
                    + Rg * sr[NZg-3] * sT[NZg-3]) * INV2DZ;
        } else {
            dpdz = (Rg * sr[k+1] * sT[k+1] - Rg * sr[k-1] * sT[k-1]) * INV2DZ;
        }
    }

    // ---- generic first derivatives (x,y) + z from smem ----
    auto d1x = [&](int f) { return (fxp[f] - fxm[f]) * INV2DX; };
    auto d1y = [&](int f) { return (fyp[f] - fym[f]) * INV2DY; };
    auto d2xy = [&](int f) {
        return (fxp[f] + fxm[f] - 2.0f * ctr[f]) * INVDX2
             + (fyp[f] + fym[f] - 2.0f * ctr[f]) * INVDY2;
    };

    // u
    const float lap_u = d2xy(0) + d2z_sm(s[0], k, INVDZ2);
    const float adv_u = u * d1x(0) + v * d1y(0) + w * d1z_sm(s[0], k, INV2DZ);
    float du = (-dpdx + MU * lap_u) * inv_rou - adv_u;

    // v
    const float lap_v = d2xy(1) + d2z_sm(s[1], k, INVDZ2);
    const float adv_v = u * d1x(1) + v * d1y(1) + w * d1z_sm(s[1], k, INV2DZ);
    float dv = (-dpdy + MU * lap_v) * inv_rou - adv_v;

    // w
    const float lap_w = d2xy(2) + d2z_sm(s[2], k, INVDZ2);
    const float adv_w = u * d1x(2) + v * d1y(2) + w * d1z_sm(s[2], k, INV2DZ);
    float dw = (-Gc * rou - dpdz + MU * lap_w) * inv_rou - adv_w;

    // rou: only -d/dx(rou*u)
    const float drou = -(fxp[3] * fxp[0] - fxm[3] * fxm[0]) * INV2DX;

    // T
    const float lap_T = d2xy(4) + d2z_sm(s[4], k, INVDZ2);
    const float adv_T = u * d1x(4) + v * d1y(4) + w * d1z_sm(s[4], k, INV2DZ);
    float dT = (KTH * lap_T) * inv_rou * (1.0f / CVc) - adv_T;

    // c
    const float adv_c = u * d1x(5) + v * d1y(5) + w * d1z_sm(s[5], k, INV2DZ);
    const float dc = -adv_c;

    // zero momentum + temperature tendencies at z walls
    if (k == 0 || k == NZg - 1) {
        du = 0.0f; dv = 0.0f; dw = 0.0f; dT = 0.0f;
    }

    out[0 * FS + idx] = du;
    out[1 * FS + idx] = dv;
    out[2 * FS + idx] = dw;
    out[3 * FS + idx] = drou;
    out[4 * FS + idx] = dT;
    out[5 * FS + idx] = dc;
}

extern "C" void kernel_launch(void* const* d_in, const int* in_sizes, int n_in,
                              void* d_out, int out_size) {
    const float* state = (const float*)d_in[0];
    float* out = (float*)d_out;
    dim3 grid(NYg, NXg);
    dim3 block(NZg);
    rbm_rhs_kernel<<<grid, block>>>(state, out);
}

// round 2
// speedup vs baseline: 1.3312x; 1.3312x over previous
#include <cuda_runtime.h>

// Rayleigh-Bénard RHS, float4-vectorized along z.
// One warp = one (i,j) z-column: lane L owns z = 4L .. 4L+3.
// z halos via warp shuffle; wall one-sided stencils (need k..k+3) live
// entirely within lane0/lane31's own float4. No shared memory.

#define NXg 256
#define NYg 256
#define NZg 128

__device__ __forceinline__ float4 operator+(float4 a, float4 b){return make_float4(a.x+b.x,a.y+b.y,a.z+b.z,a.w+b.w);}
__device__ __forceinline__ float4 operator-(float4 a, float4 b){return make_float4(a.x-b.x,a.y-b.y,a.z-b.z,a.w-b.w);}
__device__ __forceinline__ float4 operator*(float4 a, float4 b){return make_float4(a.x*b.x,a.y*b.y,a.z*b.z,a.w*b.w);}
__device__ __forceinline__ float4 operator*(float a, float4 b){return make_float4(a*b.x,a*b.y,a*b.z,a*b.w);}

// first derivative along z for one float4 (4 consecutive z), halos prev/next
__device__ __forceinline__ float4 d1z4(float4 q, float prev, float next, int lane, float s) {
    float4 r;
    r.x = (lane == 0)  ? (-3.0f*q.x + 4.0f*q.y - q.z) * s : (q.y - prev) * s;
    r.y = (q.z - q.x) * s;
    r.z = (q.w - q.y) * s;
    r.w = (lane == 31) ? ( 3.0f*q.w - 4.0f*q.z + q.y) * s : (next - q.z) * s;
    return r;
}

// second derivative along z
__device__ __forceinline__ float4 d2z4(float4 q, float prev, float next, int lane, float s) {
    float4 r;
    r.x = (lane == 0)  ? (2.0f*q.x - 5.0f*q.y + 4.0f*q.z - q.w) * s : (prev - 2.0f*q.x + q.y) * s;
    r.y = (q.x - 2.0f*q.y + q.z) * s;
    r.z = (q.y - 2.0f*q.z + q.w) * s;
    r.w = (lane == 31) ? (2.0f*q.w - 5.0f*q.z + 4.0f*q.y - q.x) * s : (q.z - 2.0f*q.w + next) * s;
    return r;
}

__global__ __launch_bounds__(256)
void rbm_rhs4_kernel(const float* __restrict__ st, float* __restrict__ out) {
    const int lane = threadIdx.x;                       // 0..31, z chunk
    const int j = blockIdx.x * blockDim.y + threadIdx.y; // y
    const int i = blockIdx.y;                            // x

    constexpr int PL4 = NYg * NZg / 4;   // x stride in float4
    constexpr int NZ4 = NZg / 4;         // y stride in float4
    constexpr int FS4 = NXg * NYg * NZg / 4;

    constexpr float CP = 1004.0f, CVc = 717.0f, MU = 1.8e-5f, KTH = 0.025f, Gc = 9.8f;
    constexpr float Rg = CP - CVc;
    constexpr float INV2DX = 0.5f * NXg;          // 128
    constexpr float INV2DY = 0.5f * NYg;          // 128
    constexpr float INV2DZ = 0.5f * (NZg - 1);    // 63.5
    constexpr float INVDX2 = (float)NXg * NXg;    // 65536
    constexpr float INVDY2 = (float)NYg * NYg;
    constexpr float INVDZ2 = (float)(NZg-1) * (NZg-1); // 16129

    const int c_i  = i * PL4 + j * NZ4 + lane;
    const int xp_i = ((i + 1) & (NXg - 1)) * PL4 + j * NZ4 + lane;
    const int xm_i = ((i - 1) & (NXg - 1)) * PL4 + j * NZ4 + lane;
    const int yp_i = i * PL4 + ((j + 1) & (NYg - 1)) * NZ4 + lane;
    const int ym_i = i * PL4 + ((j - 1) & (NYg - 1)) * NZ4 + lane;

    const float4* S = (const float4*)st;
    float4* O = (float4*)out;
    const unsigned FULL = 0xFFFFFFFFu;

    // centers of all fields
    const float4 u   = S[0*FS4 + c_i];
    const float4 v   = S[1*FS4 + c_i];
    const float4 w   = S[2*FS4 + c_i];
    const float4 rou = S[3*FS4 + c_i];
    const float4 T   = S[4*FS4 + c_i];

    const float4 inv_rou = make_float4(1.0f/rou.x, 1.0f/rou.y, 1.0f/rou.z, 1.0f/rou.w);
    const bool wallLo = (lane == 0), wallHi = (lane == 31);

    // ---------------- rou & T neighbors: pressure + T derivatives ----------
    float4 dpdx, dpdy, dpdz, lapT, d1xT, d1yT, d1zT, rxp, rxm, uxp_hold, uxm_hold;
    {
        rxp = S[3*FS4 + xp_i];
        rxm = S[3*FS4 + xm_i];
        const float4 ryp = S[3*FS4 + yp_i];
        const float4 rym = S[3*FS4 + ym_i];
        const float4 Txp = S[4*FS4 + xp_i];
        const float4 Txm = S[4*FS4 + xm_i];
        const float4 Typ = S[4*FS4 + yp_i];
        const float4 Tym = S[4*FS4 + ym_i];

        dpdx = (Rg * INV2DX) * (rxp * Txp - rxm * Txm);
        dpdy = (Rg * INV2DY) * (ryp * Typ - rym * Tym);

        const float4 p = Rg * (rou * T);
        const float p_prev = __shfl_up_sync(FULL, p.w, 1);
        const float p_next = __shfl_down_sync(FULL, p.x, 1);
        dpdz = d1z4(p, p_prev, p_next, lane, INV2DZ);

        const float T_prev = __shfl_up_sync(FULL, T.w, 1);
        const float T_next = __shfl_down_sync(FULL, T.x, 1);
        lapT = INVDX2 * (Txp + Txm - 2.0f * T) + INVDY2 * (Typ + Tym - 2.0f * T)
             + d2z4(T, T_prev, T_next, lane, INVDZ2);
        d1xT = INV2DX * (Txp - Txm);
        d1yT = INV2DY * (Typ - Tym);
        d1zT = d1z4(T, T_prev, T_next, lane, INV2DZ);
    }

    // ---------------- u field + drou ----------------
    {
        const float4 uxp = S[0*FS4 + xp_i];
        const float4 uxm = S[0*FS4 + xm_i];
        const float4 uyp = S[0*FS4 + yp_i];
        const float4 uym = S[0*FS4 + ym_i];
        const float u_prev = __shfl_up_sync(FULL, u.w, 1);
        const float u_next = __shfl_down_sync(FULL, u.x, 1);

        const float4 lap = INVDX2 * (uxp + uxm - 2.0f*u) + INVDY2 * (uyp + uym - 2.0f*u)
                         + d2z4(u, u_prev, u_next, lane, INVDZ2);
        const float4 adv = u * (INV2DX * (uxp - uxm)) + v * (INV2DY * (uyp - uym))
                         + w * d1z4(u, u_prev, u_next, lane, INV2DZ);
        float4 du = (make_float4(0,0,0,0) - dpdx + MU * lap) * inv_rou - adv;
        if (wallLo) du.x = 0.0f;
        if (wallHi) du.w = 0.0f;
        O[0*FS4 + c_i] = du;

        // drou = -d/dx(rou*u)
        float4 drou = (-INV2DX) * (rxp * uxp - rxm * uxm);
        O[3*FS4 + c_i] = drou;
    }

    // ---------------- v field ----------------
    {
        const float4 vxp = S[1*FS4 + xp_i];
        const float4 vxm = S[1*FS4 + xm_i];
        const float4 vyp = S[1*FS4 + yp_i];
        const float4 vym = S[1*FS4 + ym_i];
        const float v_prev = __shfl_up_sync(FULL, v.w, 1);
        const float v_next = __shfl_down_sync(FULL, v.x, 1);

        const float4 lap = INVDX2 * (vxp + vxm - 2.0f*v) + INVDY2 * (vyp + vym - 2.0f*v)
                         + d2z4(v, v_prev, v_next, lane, INVDZ2);
        const float4 adv = u * (INV2DX * (vxp - vxm)) + v * (INV2DY * (vyp - vym))
                         + w * d1z4(v, v_prev, v_next, lane, INV2DZ);
        float4 dv = (make_float4(0,0,0,0) - dpdy + MU * lap) * inv_rou - adv;
        if (wallLo) dv.x = 0.0f;
        if (wallHi) dv.w = 0.0f;
        O[1*FS4 + c_i] = dv;
    }

    // ---------------- w field ----------------
    {
        const float4 wxp = S[2*FS4 + xp_i];
        const float4 wxm = S[2*FS4 + xm_i];
        const float4 wyp = S[2*FS4 + yp_i];
        const float4 wym = S[2*FS4 + ym_i];
        const float w_prev = __shfl_up_sync(FULL, w.w, 1);
        const float w_next = __shfl_down_sync(FULL, w.x, 1);

        const float4 lap = INVDX2 * (wxp + wxm - 2.0f*w) + INVDY2 * (wyp + wym - 2.0f*w)
                         + d2z4(w, w_prev, w_next, lane, INVDZ2);
        const float4 adv = u * (INV2DX * (wxp - wxm)) + v * (INV2DY * (wyp - wym))
                         + w * d1z4(w, w_prev, w_next, lane, INV2DZ);
        float4 dw = ((-Gc) * rou - dpdz + MU * lap) * inv_rou - adv;
        if (wallLo) dw.x = 0.0f;
        if (wallHi) dw.w = 0.0f;
        O[2*FS4 + c_i] = dw;
    }

    // ---------------- T tendency ----------------
    {
        const float4 advT = u * d1xT + v * d1yT + w * d1zT;
        float4 dT = (KTH / CVc) * (lapT * inv_rou) - advT;
        if (wallLo) dT.x = 0.0f;
        if (wallHi) dT.w = 0.0f;
        O[4*FS4 + c_i] = dT;
    }

    // ---------------- c field ----------------
    {
        const float4 cc  = S[5*FS4 + c_i];
        const float4 cxp = S[5*FS4 + xp_i];
        const float4 cxm = S[5*FS4 + xm_i];
        const float4 cyp = S[5*FS4 + yp_i];
        const float4 cym = S[5*FS4 + ym_i];
        const float c_prev = __shfl_up_sync(FULL, cc.w, 1);
        const float c_next = __shfl_down_sync(FULL, cc.x, 1);

        const float4 adv = u * (INV2DX * (cxp - cxm)) + v * (INV2DY * (cyp - cym))
                         + w * d1z4(cc, c_prev, c_next, lane, INV2DZ);
        O[5*FS4 + c_i] = make_float4(-adv.x, -adv.y, -adv.z, -adv.w);
    }
}

extern "C" void kernel_launch(void* const* d_in, const int* in_sizes, int n_in,
                              void* d_out, int out_size) {
    const float* state = (const float*)d_in[0];
    float* out = (float*)d_out;
    dim3 block(32, 8);                 // one warp per z-column, 8 y-rows/block
    dim3 grid(NYg / 8, NXg);
    rbm_rhs4_kernel<<<grid, block>>>(state, out);
}

// round 5
// speedup vs baseline: 1.5173x; 1.1398x over previous
#include <cuda_runtime.h>

// Rayleigh-Bénard RHS, float4 along z, register-lifetime-optimized.
// One warp = one (i,j) z-column; z halos via warp shuffle.
// Each field section is self-contained so transient regs die quickly.

#define NXg 256
#define NYg 256
#define NZg 128

__device__ __forceinline__ float4 operator+(float4 a, float4 b){return make_float4(a.x+b.x,a.y+b.y,a.z+b.z,a.w+b.w);}
__device__ __forceinline__ float4 operator-(float4 a, float4 b){return make_float4(a.x-b.x,a.y-b.y,a.z-b.z,a.w-b.w);}
__device__ __forceinline__ float4 operator*(float4 a, float4 b){return make_float4(a.x*b.x,a.y*b.y,a.z*b.z,a.w*b.w);}
__device__ __forceinline__ float4 operator*(float a, float4 b){return make_float4(a*b.x,a*b.y,a*b.z,a*b.w);}

__device__ __forceinline__ float4 d1z4(float4 q, float prev, float next, int lane, float s) {
    float4 r;
    r.x = (lane == 0)  ? (-3.0f*q.x + 4.0f*q.y - q.z) * s : (q.y - prev) * s;
    r.y = (q.z - q.x) * s;
    r.z = (q.w - q.y) * s;
    r.w = (lane == 31) ? ( 3.0f*q.w - 4.0f*q.z + q.y) * s : (next - q.z) * s;
    return r;
}

__device__ __forceinline__ float4 d2z4(float4 q, float prev, float next, int lane, float s) {
    float4 r;
    r.x = (lane == 0)  ? (2.0f*q.x - 5.0f*q.y + 4.0f*q.z - q.w) * s : (prev - 2.0f*q.x + q.y) * s;
    r.y = (q.x - 2.0f*q.y + q.z) * s;
    r.z = (q.y - 2.0f*q.z + q.w) * s;
    r.w = (lane == 31) ? (2.0f*q.w - 5.0f*q.z + 4.0f*q.y - q.x) * s : (q.z - 2.0f*q.w + next) * s;
    return r;
}

__global__ __launch_bounds__(256, 3)
void rbm_rhs4_kernel(const float* __restrict__ st, float* __restrict__ out) {
    const int lane = threadIdx.x;                        // z chunk (4 pts)
    const int j = blockIdx.x * blockDim.y + threadIdx.y; // y
    const int i = blockIdx.y;                            // x

    constexpr int PL4 = NYg * NZg / 4;
    constexpr int NZ4 = NZg / 4;
    constexpr int FS4 = NXg * NYg * NZg / 4;

    constexpr float CP = 1004.0f, CVc = 717.0f, MU = 1.8e-5f, KTH = 0.025f, Gc = 9.8f;
    constexpr float Rg = CP - CVc;
    constexpr float INV2DX = 0.5f * NXg;
    constexpr float INV2DY = 0.5f * NYg;
    constexpr float INV2DZ = 0.5f * (NZg - 1);
    constexpr float INVDX2 = (float)NXg * NXg;
    constexpr float INVDY2 = (float)NYg * NYg;
    constexpr float INVDZ2 = (float)(NZg - 1) * (NZg - 1);

    const int c_i  = i * PL4 + j * NZ4 + lane;
    const int xp_i = ((i + 1) & (NXg - 1)) * PL4 + j * NZ4 + lane;
    const int xm_i = ((i - 1) & (NXg - 1)) * PL4 + j * NZ4 + lane;
    const int yp_i = i * PL4 + ((j + 1) & (NYg - 1)) * NZ4 + lane;
    const int ym_i = i * PL4 + ((j - 1) & (NYg - 1)) * NZ4 + lane;

    const float4* S = (const float4*)st;
    float4* O = (float4*)out;
    const unsigned FULL = 0xFFFFFFFFu;
    const bool wallLo = (lane == 0), wallHi = (lane == 31);

    // persistent centers
    const float4 u   = S[0*FS4 + c_i];
    const float4 v   = S[1*FS4 + c_i];
    const float4 w   = S[2*FS4 + c_i];
    const float4 rou = S[3*FS4 + c_i];
    const float4 T   = S[4*FS4 + c_i];
    const float4 inv_rou = make_float4(1.0f/rou.x, 1.0f/rou.y, 1.0f/rou.z, 1.0f/rou.w);

    // ---------------- u section (+ dpdx, drou) ----------------
    {
        const float4 uxp = S[0*FS4 + xp_i];
        const float4 uxm = S[0*FS4 + xm_i];
        const float4 uyp = S[0*FS4 + yp_i];
        const float4 uym = S[0*FS4 + ym_i];
        const float4 rxp = S[3*FS4 + xp_i];
        const float4 rxm = S[3*FS4 + xm_i];
        const float4 Txp = S[4*FS4 + xp_i];
        const float4 Txm = S[4*FS4 + xm_i];
        const float u_prev = __shfl_up_sync(FULL, u.w, 1);
        const float u_next = __shfl_down_sync(FULL, u.x, 1);

        const float4 dpdx = (Rg * INV2DX) * (rxp * Txp - rxm * Txm);
        const float4 lap = INVDX2 * (uxp + uxm - 2.0f*u) + INVDY2 * (uyp + uym - 2.0f*u)
                         + d2z4(u, u_prev, u_next, lane, INVDZ2);
        const float4 adv = u * (INV2DX * (uxp - uxm)) + v * (INV2DY * (uyp - uym))
                         + w * d1z4(u, u_prev, u_next, lane, INV2DZ);
        float4 du = (MU * lap - dpdx) * inv_rou - adv;
        if (wallLo) du.x = 0.0f;
        if (wallHi) du.w = 0.0f;
        O[0*FS4 + c_i] = du;

        float4 drou = (-INV2DX) * (rxp * uxp - rxm * uxm);
        O[3*FS4 + c_i] = drou;
    }

    // ---------------- v section (+ dpdy) ----------------
    {
        const float4 vxp = S[1*FS4 + xp_i];
        const float4 vxm = S[1*FS4 + xm_i];
        const float4 vyp = S[1*FS4 + yp_i];
        const float4 vym = S[1*FS4 + ym_i];
        const float4 ryp = S[3*FS4 + yp_i];
        const float4 rym = S[3*FS4 + ym_i];
        const float4 Typ = S[4*FS4 + yp_i];
        const float4 Tym = S[4*FS4 + ym_i];
        const float v_prev = __shfl_up_sync(FULL, v.w, 1);
        const float v_next = __shfl_down_sync(FULL, v.x, 1);

        const float4 dpdy = (Rg * INV2DY) * (ryp * Typ - rym * Tym);
        const float4 lap = INVDX2 * (vxp + vxm - 2.0f*v) + INVDY2 * (vyp + vym - 2.0f*v)
                         + d2z4(v, v_prev, v_next, lane, INVDZ2);
        const float4 adv = u * (INV2DX * (vxp - vxm)) + v * (INV2DY * (vyp - vym))
                         + w * d1z4(v, v_prev, v_next, lane, INV2DZ);
        float4 dv = (MU * lap - dpdy) * inv_rou - adv;
        if (wallLo) dv.x = 0.0f;
        if (wallHi) dv.w = 0.0f;
        O[1*FS4 + c_i] = dv;
    }

    // ---------------- T section (reload T neighbors: L1 hits) ------------
    {
        const float4 Txp = S[4*FS4 + xp_i];
        const float4 Txm = S[4*FS4 + xm_i];
        const float4 Typ = S[4*FS4 + yp_i];
        const float4 Tym = S[4*FS4 + ym_i];
        const float T_prev = __shfl_up_sync(FULL, T.w, 1);
        const float T_next = __shfl_down_sync(FULL, T.x, 1);

        const float4 lap = INVDX2 * (Txp + Txm - 2.0f*T) + INVDY2 * (Typ + Tym - 2.0f*T)
                         + d2z4(T, T_prev, T_next, lane, INVDZ2);
        const float4 adv = u * (INV2DX * (Txp - Txm)) + v * (INV2DY * (Typ - Tym))
                         + w * d1z4(T, T_prev, T_next, lane, INV2DZ);
        float4 dT = (KTH / CVc) * (lap * inv_rou) - adv;
        if (wallLo) dT.x = 0.0f;
        if (wallHi) dT.w = 0.0f;
        O[4*FS4 + c_i] = dT;
    }

    // ---------------- w section (dpdz from centers) ----------------
    {
        const float4 wxp = S[2*FS4 + xp_i];
        const float4 wxm = S[2*FS4 + xm_i];
        const float4 wyp = S[2*FS4 + yp_i];
        const float4 wym = S[2*FS4 + ym_i];
        const float w_prev = __shfl_up_sync(FULL, w.w, 1);
        const float w_next = __shfl_down_sync(FULL, w.x, 1);

        const float4 p = Rg * (rou * T);
        const float p_prev = __shfl_up_sync(FULL, p.w, 1);
        const float p_next = __shfl_down_sync(FULL, p.x, 1);
        const float4 dpdz = d1z4(p, p_prev, p_next, lane, INV2DZ);

        const float4 lap = INVDX2 * (wxp + wxm - 2.0f*w) + INVDY2 * (wyp + wym - 2.0f*w)
                         + d2z4(w, w_prev, w_next, lane, INVDZ2);
        const float4 adv = u * (INV2DX * (wxp - wxm)) + v * (INV2DY * (wyp - wym))
                         + w * d1z4(w, w_prev, w_next, lane, INV2DZ);
        float4 dw = (MU * lap - dpdz - Gc * rou) * inv_rou - adv;
        if (wallLo) dw.x = 0.0f;
        if (wallHi) dw.w = 0.0f;
        O[2*FS4 + c_i] = dw;
    }

    // ---------------- c section ----------------
    {
        const float4 cc  = S[5*FS4 + c_i];
        const float4 cxp = S[5*FS4 + xp_i];
        const float4 cxm = S[5*FS4 + xm_i];
        const float4 cyp = S[5*FS4 + yp_i];
        const float4 cym = S[5*FS4 + ym_i];
        const float c_prev = __shfl_up_sync(FULL, cc.w, 1);
        const float c_next = __shfl_down_sync(FULL, cc.x, 1);

        const float4 adv = u * (INV2DX * (cxp - cxm)) + v * (INV2DY * (cyp - cym))
                         + w * d1z4(cc, c_prev, c_next, lane, INV2DZ);
        O[5*FS4 + c_i] = make_float4(-adv.x, -adv.y, -adv.z, -adv.w);
    }
}

extern "C" void kernel_launch(void* const* d_in, const int* in_sizes, int n_in,
                              void* d_out, int out_size) {
    const float* state = (const float*)d_in[0];
    float* out = (float*)d_out;
    dim3 block(32, 8);
    dim3 grid(NYg / 8, NXg);
    rbm_rhs4_kernel<<<grid, block>>>(state, out);
}